// round 5
// baseline (speedup 1.0000x reference)
#include <cuda_runtime.h>
#include <math.h>

typedef unsigned long long ull;

// ---------------------------------------------------------------------------
// f32x2 helpers. No packing of fresh scalars in the hot loop: aligned pairs
// come from LDS.64; shifted pairs are built from neighboring pair halves
// (2 SASS MOVs each, resolved by ptxas register coalescing where possible).
// ---------------------------------------------------------------------------
__device__ __forceinline__ void ffma2(ull& d, ull a, ull b) {
    asm("fma.rn.f32x2 %0, %1, %2, %0;" : "+l"(d) : "l"(a), "l"(b));
}
// (hi(a), lo(b))
__device__ __forceinline__ ull combine(ull a, ull b) {
    ull r;
    asm("{ .reg .f32 al, ah, bl, bh;\n\t"
        "mov.b64 {al, ah}, %1;\n\t"
        "mov.b64 {bl, bh}, %2;\n\t"
        "mov.b64 %0, {ah, bl}; }"
        : "=l"(r) : "l"(a), "l"(b));
    return r;
}
// (hi(a), t)
__device__ __forceinline__ ull combine_tail(ull a, float t) {
    ull r;
    asm("{ .reg .f32 al, ah;\n\t"
        "mov.b64 {al, ah}, %1;\n\t"
        "mov.b64 %0, {ah, %2}; }"
        : "=l"(r) : "l"(a), "f"(t));
    return r;
}
__device__ __forceinline__ void unpack2(ull v, float& lo, float& hi) {
    asm("mov.b64 {%0, %1}, %2;" : "=f"(lo), "=f"(hi) : "l"(v));
}

// ---------------------------------------------------------------------------
// Scratch (no allocations allowed -> static __device__ arrays)
// ---------------------------------------------------------------------------
__device__ float g_h1[256 * 3 * 50625];  // [B,3,15,15,15,15]
__device__ float g_h2[256 * 3 * 20736];  // [B,3,12,12,12,12]
__device__ float g_h3[256 * 4 * 6561];   // [B,4,9,9,9,9]
__device__ float g_h4[256 * 5 * 1296];   // [B,5,6,6,6,6]
__device__ float g_h5[256 * 5 * 256];    // [B,5,4,4,4,4] == [B,1280]

// Padded z-row stride: smallest even >= S whose half is odd ->
// pair-granular addresses 8B-aligned and conflict-free (odd pair stride).
__host__ __device__ constexpr int rs_of(int S) {
    int e = (S + 1) & ~1;
    return ((e / 2) & 1) ? e : e + 2;
}
__host__ __device__ constexpr int slabp_of(int S, int K) {
    return K * S * S * rs_of(S) + 8;   // +8 floats pad for tail over-read
}
__host__ __device__ constexpr int smem_of(int S, int K, int CIN, int COUT, int NS) {
    return (2 * COUT * CIN * K * K * K * K + NS * slabp_of(S, K)) * 4;
}

// ---------------------------------------------------------------------------
// 4D conv + bias + relu, f32x2 packed math (oz-pairs), zero hot-loop packing.
//   in : [B,CIN,S,S,S,S]; w: [COUT,CIN,K,K,K,K]; out: [B,COUT,T,T,T,T]
// Block = NS slices of (b,ow); each slice's oz range split ZSPL ways.
// Thread = (slice, z-chunk, ox, oy); acc[COUT][P] oz-pairs in 64-bit regs.
// ---------------------------------------------------------------------------
template <int S, int K, int CIN, int COUT, int ZSPL, int NS, int BLK, int MINB>
__global__ void __launch_bounds__(BLK, MINB)
conv4d_relu_f2(const float* __restrict__ x,
               const float* __restrict__ w,
               const float* __restrict__ bias,
               float* __restrict__ y)
{
    constexpr int T     = S - K + 1;
    constexpr int OZB   = (T + ZSPL - 1) / ZSPL;   // oz per chunk (even if ZSPL>1)
    constexpr int P     = (OZB + 1) / 2;           // packed pairs per chunk
    constexpr int RS    = rs_of(S);
    constexpr int S3    = S * S * S;
    constexpr int SLABP = slabp_of(S, K);
    constexpr int WN    = COUT * CIN * K * K * K * K;
    constexpr int NE    = P + (K - 1) / 2;         // aligned pairs (LDS.64)
    constexpr int NO    = (K >= 2) ? P + (K - 2) / 2 : 0;  // shifted pairs
    constexpr bool TAIL = (K % 2) == 0;            // last o needs scalar tail

    static_assert(ZSPL == 1 || (OZB % 2) == 0, "oz0 must be even");

    extern __shared__ float sm[];
    ull*   swu   = reinterpret_cast<ull*>(sm);     // [WN] (w,w) pairs
    float* slab0 = sm + 2 * WN;

    const int tid = threadIdx.x;

    {   // stage duplicated weights
        float2* wd = reinterpret_cast<float2*>(sm);
        for (int i = tid; i < WN; i += BLK) {
            float v = w[i];
            wd[i] = make_float2(v, v);
        }
    }

    constexpr int TT   = T * T;
    constexpr int PERS = ZSPL * TT;
    const int s   = tid / PERS;
    const int r0  = tid - s * PERS;
    const int zc  = r0 / TT;
    const int rr  = r0 - zc * TT;
    const int ox  = rr / T;
    const int oy  = rr - ox * T;
    const bool active = (tid < NS * PERS);
    const int slice = blockIdx.x * NS + s;
    const int b_t   = slice / T;
    const int ow_t  = slice % T;
    const int oz0   = zc * OZB;
    const float* slab = slab0 + s * SLABP;

    ull acc[COUT][P];
#pragma unroll
    for (int co = 0; co < COUT; ++co)
#pragma unroll
        for (int p = 0; p < P; ++p) acc[co][p] = 0ull;

    for (int ci = 0; ci < CIN; ++ci) {
        __syncthreads();   // protect slabs from previous iteration's readers
        for (int i = tid; i < NS * K * S3; i += BLK) {
            int ss = i / (K * S3);
            int r  = i - ss * (K * S3);
            int sl = blockIdx.x * NS + ss;
            int bb = sl / T, oww = sl % T;
            int kw = r / S3;
            int r1 = r - kw * S3;
            int xx = r1 / (S * S);
            int r2 = r1 - xx * (S * S);
            int yy = r2 / S;
            int zz = r2 - yy * S;
            slab0[ss * SLABP + ((kw * S + xx) * S + yy) * RS + zz] =
                x[((size_t)(bb * CIN + ci) * S + oww) * S3 + r];
        }
        __syncthreads();

        if (active) {
#pragma unroll 1
            for (int kw = 0; kw < K; ++kw)
#pragma unroll 1
            for (int kx = 0; kx < K; ++kx)
#pragma unroll 1
            for (int ky = 0; ky < K; ++ky) {
                const float* row =
                    &slab[((kw * S + ox + kx) * S + oy + ky) * RS + oz0];
                const ull* rowp = reinterpret_cast<const ull*>(row);  // 8B aligned

                ull e[NE];
#pragma unroll
                for (int i = 0; i < NE; ++i) e[i] = rowp[i];

                ull o[NO > 0 ? NO : 1];
#pragma unroll
                for (int i = 0; i < NO - (TAIL ? 1 : 0); ++i)
                    o[i] = combine(e[i], e[i + 1]);
                if (TAIL)
                    o[NO - 1] = combine_tail(e[NO - 1], row[2 * NO]);

#pragma unroll
                for (int co = 0; co < COUT; ++co) {
                    ull wp[K];
#pragma unroll
                    for (int kz = 0; kz < K; ++kz)
                        wp[kz] = swu[((((co * CIN + ci) * K + kw) * K + kx) * K + ky) * K + kz];
#pragma unroll
                    for (int p = 0; p < P; ++p)
#pragma unroll
                        for (int kz = 0; kz < K; ++kz) {
                            ull a = ((kz & 1) == 0) ? e[p + kz / 2]
                                                    : o[p + (kz - 1) / 2];
                            ffma2(acc[co][p], a, wp[kz]);
                        }
                }
            }
        }
    }

    if (active) {
#pragma unroll
        for (int co = 0; co < COUT; ++co) {
            float bv = bias[co];
            float* yb = y + (((((size_t)b_t * COUT + co) * T + ow_t) * T + ox) * T + oy) * T + oz0;
#pragma unroll
            for (int p = 0; p < P; ++p) {
                float lo, hi;
                unpack2(acc[co][p], lo, hi);
                if (oz0 + 2 * p < T) {
                    float vlo = lo + bv;
                    yb[2 * p] = vlo > 0.f ? vlo : 0.f;
                }
                if (oz0 + 2 * p + 1 < T) {
                    float vhi = hi + bv;
                    yb[2 * p + 1] = vhi > 0.f ? vhi : 0.f;
                }
            }
        }
    }
}

// ---------------------------------------------------------------------------
// Dense head: relu(h @ dw1.T + db1) @ dw2.T + db2 -> softmax over 2 classes.
// ---------------------------------------------------------------------------
__global__ void dense_head(const float* __restrict__ h,
                           const float* __restrict__ dw1,
                           const float* __restrict__ db1,
                           const float* __restrict__ dw2,
                           const float* __restrict__ db2,
                           float* __restrict__ out)
{
    __shared__ float hb[1280];
    __shared__ float a[33];
    const int b   = blockIdx.x;
    const int tid = threadIdx.x;

    for (int i = tid; i < 1280; i += blockDim.x) hb[i] = h[b * 1280 + i];
    __syncthreads();

    const int warp = tid >> 5, lane = tid & 31;
    const int nwarps = blockDim.x >> 5;
    for (int co = warp; co < 33; co += nwarps) {
        float s = 0.f;
        for (int i = lane; i < 1280; i += 32) s += hb[i] * dw1[co * 1280 + i];
#pragma unroll
        for (int o = 16; o > 0; o >>= 1) s += __shfl_down_sync(0xffffffffu, s, o);
        if (lane == 0) {
            float v = s + db1[co];
            a[co] = v > 0.f ? v : 0.f;
        }
    }
    __syncthreads();

    if (tid == 0) {
        float z0 = db2[0], z1 = db2[1];
#pragma unroll
        for (int i = 0; i < 33; ++i) {
            z0 += a[i] * dw2[i];
            z1 += a[i] * dw2[33 + i];
        }
        float m  = fmaxf(z0, z1);
        float e0 = expf(z0 - m), e1 = expf(z1 - m);
        float inv = 1.f / (e0 + e1);
        out[2 * b]     = e0 * inv;
        out[2 * b + 1] = e1 * inv;
    }
}

// ---------------------------------------------------------------------------
// Launch
// ---------------------------------------------------------------------------
extern "C" void kernel_launch(void* const* d_in, const int* in_sizes, int n_in,
                              void* d_out, int out_size)
{
    const float* x   = (const float*)d_in[0];
    const float* w1  = (const float*)d_in[1];
    const float* b1  = (const float*)d_in[2];
    const float* w2  = (const float*)d_in[3];
    const float* b2  = (const float*)d_in[4];
    const float* w3  = (const float*)d_in[5];
    const float* b3  = (const float*)d_in[6];
    const float* w4  = (const float*)d_in[7];
    const float* b4  = (const float*)d_in[8];
    const float* w5  = (const float*)d_in[9];
    const float* b5  = (const float*)d_in[10];
    const float* dw1 = (const float*)d_in[11];
    const float* db1 = (const float*)d_in[12];
    const float* dw2 = (const float*)d_in[13];
    const float* db2 = (const float*)d_in[14];
    float* out = (float*)d_out;

    float *h1, *h2, *h3, *h4, *h5;
    cudaGetSymbolAddress((void**)&h1, g_h1);
    cudaGetSymbolAddress((void**)&h2, g_h2);
    cudaGetSymbolAddress((void**)&h3, g_h3);
    cudaGetSymbolAddress((void**)&h4, g_h4);
    cudaGetSymbolAddress((void**)&h5, g_h5);

    // L1: S=18 RS=18  ZSPL=2 NS=1 BLK=480 (450 act) smem= 99,488B -> 2 blk/SM (30 warps)
    // L2: S=15 RS=18  ZSPL=2 NS=1 BLK=288 (288 act) smem= 83,264B -> 2 blk/SM (18 warps)
    // L3: S=12 RS=14  ZSPL=1 NS=2 BLK=192 (162 act) smem= 89,152B -> 2 blk/SM (12 warps)
    // L4: S=9  RS=10  ZSPL=1 NS=4 BLK=160 (144 act) smem= 92,928B -> 2 blk/SM (10 warps)
    // L5: S=6  RS=6   ZSPL=1 NS=8 BLK=128 (128 act) smem= 37,192B -> 4 blk/SM (16 warps)
    constexpr int sm1 = smem_of(18, 4, 1, 3, 1);
    constexpr int sm2 = smem_of(15, 4, 3, 3, 1);
    constexpr int sm3 = smem_of(12, 4, 3, 4, 2);
    constexpr int sm4 = smem_of(9, 4, 4, 5, 4);
    constexpr int sm5 = smem_of(6, 3, 5, 5, 8);

    cudaFuncSetAttribute((conv4d_relu_f2<18, 4, 1, 3, 2, 1, 480, 2>),
                         cudaFuncAttributeMaxDynamicSharedMemorySize, sm1);
    cudaFuncSetAttribute((conv4d_relu_f2<15, 4, 3, 3, 2, 1, 288, 2>),
                         cudaFuncAttributeMaxDynamicSharedMemorySize, sm2);
    cudaFuncSetAttribute((conv4d_relu_f2<12, 4, 3, 4, 1, 2, 192, 2>),
                         cudaFuncAttributeMaxDynamicSharedMemorySize, sm3);
    cudaFuncSetAttribute((conv4d_relu_f2<9, 4, 4, 5, 1, 4, 160, 2>),
                         cudaFuncAttributeMaxDynamicSharedMemorySize, sm4);
    cudaFuncSetAttribute((conv4d_relu_f2<6, 3, 5, 5, 1, 8, 128, 4>),
                         cudaFuncAttributeMaxDynamicSharedMemorySize, sm5);

    conv4d_relu_f2<18, 4, 1, 3, 2, 1, 480, 2><<<256 * 15,     480, sm1>>>(x,  w1, b1, h1);
    conv4d_relu_f2<15, 4, 3, 3, 2, 1, 288, 2><<<256 * 12,     288, sm2>>>(h1, w2, b2, h2);
    conv4d_relu_f2<12, 4, 3, 4, 1, 2, 192, 2><<<256 * 9 / 2,  192, sm3>>>(h2, w3, b3, h3);
    conv4d_relu_f2< 9, 4, 4, 5, 1, 4, 160, 2><<<256 * 6 / 4,  160, sm4>>>(h3, w4, b4, h4);
    conv4d_relu_f2< 6, 3, 5, 5, 1, 8, 128, 4><<<256 * 4 / 8,  128, sm5>>>(h4, w5, b5, h5);
    dense_head<<<256, 256>>>(h5, dw1, db1, dw2, db2, out);
}